// round 15
// baseline (speedup 1.0000x reference)
#include <cuda_runtime.h>
#include <cuda_fp16.h>
#include <cstdint>
#include <stdint.h>
#include <math.h>
#include <math_constants.h>

// Problem constants
#define BATCH  32
#define SEQ    4096
#define DDIM   1024
#define NTOK   (BATCH*SEQ)     // 131072
#define NHEAD  16
#define HD     64
#define RLAT   64
#define SCALE  0.125f          // R^-0.5

// ---------------------------------------------------------------------------
// Device scratch (static allocation; no cudaMalloc allowed)
// ---------------------------------------------------------------------------
__device__ float  g_P   [DDIM*DDIM];           // folded kv@wo (fp32, used by k_final)
__device__ __half g_W1T [DDIM*DDIM];           // w1^T fp16 (n-major, k contiguous)
__device__ __half g_B1  [DDIM*DDIM];           // Wl^T  fp16 (n-major, k contiguous)
__device__ int8_t g_B1q [DDIM*DDIM];           // Wl^T  int8
__device__ float  g_sbB [DDIM];                // per-row scale of B1q
__device__ __half g_B2  [DDIM*DDIM];           // Q1^T  fp16
__device__ int8_t g_xq  [(size_t)NTOK*DDIM];   // x int8 (128 MB)
__device__ float  g_sa  [NTOK];                // per-row scale of x
__device__ __half g_attnH[(size_t)NTOK*DDIM];  // softmax(attn) fp16 (256 MB)
__device__ float  g_Gsum[BATCH*DDIM];
__device__ float  g_Asum[BATCH*DDIM];

// ---------------------------------------------------------------------------
// Portable PTX helpers (sm_80+ ISA — harness emits compute_103 PTX)
// ---------------------------------------------------------------------------
__device__ __forceinline__ uint32_t smem_u32(const void* p) {
    uint32_t a;
    asm("{ .reg .u64 t; cvta.to.shared.u64 t, %1; cvt.u32.u64 %0, t; }" : "=r"(a) : "l"(p));
    return a;
}
__device__ __forceinline__ void ldm_x4(uint32_t* r, uint32_t a) {
    asm volatile("ldmatrix.sync.aligned.m8n8.x4.shared.b16 {%0,%1,%2,%3}, [%4];"
        : "=r"(r[0]), "=r"(r[1]), "=r"(r[2]), "=r"(r[3]) : "r"(a));
}
__device__ __forceinline__ void mma16816(float* c, const uint32_t* a, const uint32_t* b) {
    asm volatile("mma.sync.aligned.m16n8k16.row.col.f32.f16.f16.f32 "
        "{%0,%1,%2,%3}, {%4,%5,%6,%7}, {%8,%9}, {%0,%1,%2,%3};"
        : "+f"(c[0]), "+f"(c[1]), "+f"(c[2]), "+f"(c[3])
        : "r"(a[0]), "r"(a[1]), "r"(a[2]), "r"(a[3]), "r"(b[0]), "r"(b[1]));
}
__device__ __forceinline__ void imma16832(int* c, const uint32_t* a, const uint32_t* b) {
    asm volatile("mma.sync.aligned.m16n8k32.row.col.s32.s8.s8.s32 "
        "{%0,%1,%2,%3}, {%4,%5,%6,%7}, {%8,%9}, {%0,%1,%2,%3};"
        : "+r"(c[0]), "+r"(c[1]), "+r"(c[2]), "+r"(c[3])
        : "r"(a[0]), "r"(a[1]), "r"(a[2]), "r"(a[3]), "r"(b[0]), "r"(b[1]));
}
#define CP_ASYNC16(dst, src) \
    asm volatile("cp.async.cg.shared.global [%0], [%1], 16;" :: "r"(dst), "l"(src) : "memory")
#define CP_COMMIT() asm volatile("cp.async.commit_group;" ::: "memory")
#define CP_WAIT0()  asm volatile("cp.async.wait_group 0;" ::: "memory")

// 16B-unit XOR swizzle: row stride 64B, unit u in 0..3
__device__ __forceinline__ int swz(int row, int u) {
    return row * 64 + ((u ^ ((row >> 1) & 3)) << 4);
}

#define STG      16384         // bytes per stage (64B/row x 128/256 rows)
#define OFF_B    8192
#define SMEM_M1  67584         // epilogue Cs 128*132*4 (>= 2*STG)
#define SMEM_M2  32768         // 2*STG

// ---------------------------------------------------------------------------
// wm_gemm<MODE, AHALF>: fp16 single-pass, f32 accum (round-9 proven config)
//   MODE 0: store C^T fp16 (B2 build)   MODE 2: bias+gelu colsum (GEMM2)
// ---------------------------------------------------------------------------
template<int MODE, int AHALF>
__global__ void __launch_bounds__(256, 2)
wm_gemm(const float* __restrict__ Af, const __half* __restrict__ Ah16,
        const __half* __restrict__ B,
        const float* __restrict__ bias,
        __half* __restrict__ outH, float* __restrict__ redOut)
{
    extern __shared__ char sm[];
    const uint32_t smb = smem_u32(sm);
    const int tid = threadIdx.x;
    const int lane = tid & 31, wid = tid >> 5;
    const int wm = wid & 1;
    const int wncol = (wid >> 1) * 32;
    const int row0 = blockIdx.y * 128, col0 = blockIdx.x * 128;

    float acc[4][4][4];
    #pragma unroll
    for (int i = 0; i < 4; i++)
        #pragma unroll
        for (int j = 0; j < 4; j++)
            #pragma unroll
            for (int r = 0; r < 4; r++) acc[i][j][r] = 0.f;

    const int u0r = (tid + 0)   >> 2, u0u = (tid + 0)   & 3;
    const int u1r = (tid + 256) >> 2, u1u = (tid + 256) & 3;

    auto loadB = [&](int kc, int s) {
        uint32_t base = smb + s * STG;
        CP_ASYNC16(base + OFF_B + swz(u0r, u0u), B + (size_t)(col0 + u0r) * DDIM + kc * 32 + u0u * 8);
        CP_ASYNC16(base + OFF_B + swz(u1r, u1u), B + (size_t)(col0 + u1r) * DDIM + kc * 32 + u1u * 8);
    };
    auto loadA_async = [&](int kc, int s) {
        uint32_t base = smb + s * STG;
        CP_ASYNC16(base + swz(u0r, u0u), Ah16 + (size_t)(row0 + u0r) * DDIM + kc * 32 + u0u * 8);
        CP_ASYNC16(base + swz(u1r, u1u), Ah16 + (size_t)(row0 + u1r) * DDIM + kc * 32 + u1u * 8);
    };
    auto loadA_f32 = [&](int kc, float4* av) {
        const float* a0 = Af + (size_t)(row0 + u0r) * DDIM + kc * 32 + u0u * 8;
        const float* a1 = Af + (size_t)(row0 + u1r) * DDIM + kc * 32 + u1u * 8;
        av[0] = *(const float4*)(a0);
        av[1] = *(const float4*)(a0 + 4);
        av[2] = *(const float4*)(a1);
        av[3] = *(const float4*)(a1 + 4);
    };
    auto stsA = [&](const float4* av, int s) {
        char* base = sm + (size_t)s * STG;
        #pragma unroll
        for (int i = 0; i < 2; i++) {
            float4 v0 = av[2*i], v1 = av[2*i+1];
            __half2 h0 = __floats2half2_rn(v0.x, v0.y);
            __half2 h1 = __floats2half2_rn(v0.z, v0.w);
            __half2 h2 = __floats2half2_rn(v1.x, v1.y);
            __half2 h3 = __floats2half2_rn(v1.z, v1.w);
            int r = i ? u1r : u0r, u = i ? u1u : u0u;
            *(uint4*)(base + swz(r, u)) =
                make_uint4(*(uint32_t*)&h0, *(uint32_t*)&h1, *(uint32_t*)&h2, *(uint32_t*)&h3);
        }
    };

    loadB(0, 0);
    if (AHALF) loadA_async(0, 0);
    CP_COMMIT();
    if (!AHALF) { float4 av[4]; loadA_f32(0, av); stsA(av, 0); }
    CP_WAIT0(); __syncthreads();

    for (int kc = 0; kc < 32; kc++) {
        const int cur = kc & 1;
        float4 av[4];
        if (kc < 31) {
            loadB(kc + 1, cur ^ 1);
            if (AHALF) loadA_async(kc + 1, cur ^ 1);
            CP_COMMIT();
            if (!AHALF) loadA_f32(kc + 1, av);
        }
        const uint32_t sA = smb + cur * STG;
        #pragma unroll
        for (int kk = 0; kk < 2; kk++) {
            uint32_t ah[4][4], bh[4][2];
            #pragma unroll
            for (int mt = 0; mt < 4; mt++) {
                int arow = wm * 64 + mt * 16 + (lane & 7) + ((lane >> 3) & 1) * 8;
                int au   = kk * 2 + (lane >> 4);
                ldm_x4(ah[mt], sA + swz(arow, au));
            }
            #pragma unroll
            for (int nt2 = 0; nt2 < 2; nt2++) {
                int brow = wncol + nt2 * 16 + ((lane >> 4) << 3) + (lane & 7);
                int bu   = kk * 2 + ((lane >> 3) & 1);
                uint32_t r4[4];
                ldm_x4(r4, sA + OFF_B + swz(brow, bu));
                bh[2*nt2][0] = r4[0]; bh[2*nt2][1] = r4[1];
                bh[2*nt2+1][0] = r4[2]; bh[2*nt2+1][1] = r4[3];
            }
            #pragma unroll
            for (int mt = 0; mt < 4; mt++)
                #pragma unroll
                for (int nt = 0; nt < 4; nt++)
                    mma16816(acc[mt][nt], ah[mt], bh[nt]);
        }
        if (!AHALF && kc < 31) stsA(av, cur ^ 1);
        CP_WAIT0(); __syncthreads();
    }

    const int batch = row0 >> 12;

    if (MODE == 0) {
        float* Cs = (float*)sm;
        #pragma unroll
        for (int mt = 0; mt < 4; mt++)
            #pragma unroll
            for (int nt = 0; nt < 4; nt++) {
                int row = wm * 64 + mt * 16 + (lane >> 2);
                int col = wncol + nt * 8 + (lane & 3) * 2;
                *(float2*)&Cs[row * 132 + col]       = make_float2(acc[mt][nt][0], acc[mt][nt][1]);
                *(float2*)&Cs[(row + 8) * 132 + col] = make_float2(acc[mt][nt][2], acc[mt][nt][3]);
            }
        __syncthreads();
        const int n = tid >> 1, half = tid & 1;
        __half* dst = outH + (size_t)(col0 + n) * DDIM + row0 + half * 64;
        #pragma unroll
        for (int j = 0; j < 32; j++) {
            __half2 p = __floats2half2_rn(Cs[(half*64 + 2*j    ) * 132 + n],
                                          Cs[(half*64 + 2*j + 1) * 132 + n]);
            ((uint32_t*)dst)[j] = *(uint32_t*)&p;
        }
    }

    if (MODE == 2) {
        float bv[4][2];
        #pragma unroll
        for (int nt = 0; nt < 4; nt++)
            #pragma unroll
            for (int p = 0; p < 2; p++)
                bv[nt][p] = __ldg(&bias[col0 + wncol + nt * 8 + (lane & 3) * 2 + p]);
        float cs[4][2];
        #pragma unroll
        for (int nt = 0; nt < 4; nt++) { cs[nt][0] = 0.f; cs[nt][1] = 0.f; }
        #pragma unroll
        for (int mt = 0; mt < 4; mt++)
            #pragma unroll
            for (int nt = 0; nt < 4; nt++)
                #pragma unroll
                for (int rg = 0; rg < 4; rg++) {
                    float z = acc[mt][nt][rg] + bv[nt][rg & 1];
                    float g = 0.5f * z * (1.f + erff(z * 0.70710678118654752f));
                    cs[nt][rg & 1] += g;
                }
        float* red = (float*)sm;
        const int slot = wm * 8 + (lane >> 2);
        __syncthreads();
        #pragma unroll
        for (int nt = 0; nt < 4; nt++)
            #pragma unroll
            for (int p = 0; p < 2; p++)
                red[(wncol + nt * 8 + (lane & 3) * 2 + p) * 17 + slot] = cs[nt][p];
        __syncthreads();
        if (tid < 128) {
            float s2 = 0.f;
            #pragma unroll
            for (int t = 0; t < 16; t++) s2 += red[tid * 17 + t];
            atomicAdd(&redOut[batch * DDIM + col0 + tid], s2);
        }
    }
}

// ---------------------------------------------------------------------------
// wm_gemm_i8: GEMM1 via int8 IMMA k32, single pass. C scaled by sa[row]*sb[col].
// Per-head softmax, attn fp16 out, colsum -> Asum. NKC=16 chunks of k=64.
// Staging byte-layout identical to fp16 BK=32 (64 B/row), so all fragment
// address formulas carry over.
// ---------------------------------------------------------------------------
__global__ void __launch_bounds__(256, 2)
wm_gemm_i8(const int8_t* __restrict__ Aq, const int8_t* __restrict__ Bq,
           const float* __restrict__ saA, const float* __restrict__ sbB,
           __half* __restrict__ attnOut, float* __restrict__ redOut)
{
    extern __shared__ char sm[];
    const uint32_t smb = smem_u32(sm);
    const int tid = threadIdx.x;
    const int lane = tid & 31, wid = tid >> 5;
    const int wm = wid & 1;
    const int wncol = (wid >> 1) * 32;
    const int row0 = blockIdx.y * 128, col0 = blockIdx.x * 128;

    int acc[4][4][4];
    #pragma unroll
    for (int i = 0; i < 4; i++)
        #pragma unroll
        for (int j = 0; j < 4; j++)
            #pragma unroll
            for (int r = 0; r < 4; r++) acc[i][j][r] = 0;

    const int u0r = (tid + 0)   >> 2, u0u = (tid + 0)   & 3;
    const int u1r = (tid + 256) >> 2, u1u = (tid + 256) & 3;

    auto loadAB = [&](int kc, int s) {
        uint32_t base = smb + s * STG;
        CP_ASYNC16(base + swz(u0r, u0u),         Aq + (size_t)(row0 + u0r) * DDIM + kc * 64 + u0u * 16);
        CP_ASYNC16(base + swz(u1r, u1u),         Aq + (size_t)(row0 + u1r) * DDIM + kc * 64 + u1u * 16);
        CP_ASYNC16(base + OFF_B + swz(u0r, u0u), Bq + (size_t)(col0 + u0r) * DDIM + kc * 64 + u0u * 16);
        CP_ASYNC16(base + OFF_B + swz(u1r, u1u), Bq + (size_t)(col0 + u1r) * DDIM + kc * 64 + u1u * 16);
    };

    loadAB(0, 0); CP_COMMIT();
    CP_WAIT0(); __syncthreads();

    for (int kc = 0; kc < 16; kc++) {
        const int cur = kc & 1;
        if (kc < 15) { loadAB(kc + 1, cur ^ 1); CP_COMMIT(); }
        const uint32_t sA = smb + cur * STG;
        #pragma unroll
        for (int kk = 0; kk < 2; kk++) {    // each kk = 32 int8 k-values
            uint32_t ah[4][4], bh[4][2];
            #pragma unroll
            for (int mt = 0; mt < 4; mt++) {
                int arow = wm * 64 + mt * 16 + (lane & 7) + ((lane >> 3) & 1) * 8;
                int au   = kk * 2 + (lane >> 4);
                ldm_x4(ah[mt], sA + swz(arow, au));
            }
            #pragma unroll
            for (int nt2 = 0; nt2 < 2; nt2++) {
                int brow = wncol + nt2 * 16 + ((lane >> 4) << 3) + (lane & 7);
                int bu   = kk * 2 + ((lane >> 3) & 1);
                uint32_t r4[4];
                ldm_x4(r4, sA + OFF_B + swz(brow, bu));
                bh[2*nt2][0] = r4[0]; bh[2*nt2][1] = r4[1];
                bh[2*nt2+1][0] = r4[2]; bh[2*nt2+1][1] = r4[3];
            }
            #pragma unroll
            for (int mt = 0; mt < 4; mt++)
                #pragma unroll
                for (int nt = 0; nt < 4; nt++)
                    imma16832(acc[mt][nt], ah[mt], bh[nt]);
        }
        CP_WAIT0(); __syncthreads();
    }

    const int batch = row0 >> 12;

    // ---- epilogue: dequantize while staging Cs, then softmax + Asum (round-9 shape)
    float* Cs = (float*)sm;
    {
        float sav[4][2], sbv[4][2];
        #pragma unroll
        for (int mt = 0; mt < 4; mt++) {
            int row = wm * 64 + mt * 16 + (lane >> 2);
            sav[mt][0] = __ldg(&saA[row0 + row]);
            sav[mt][1] = __ldg(&saA[row0 + row + 8]);
        }
        #pragma unroll
        for (int nt = 0; nt < 4; nt++) {
            int col = wncol + nt * 8 + (lane & 3) * 2;
            sbv[nt][0] = __ldg(&sbB[col0 + col]);
            sbv[nt][1] = __ldg(&sbB[col0 + col + 1]);
        }
        #pragma unroll
        for (int mt = 0; mt < 4; mt++)
            #pragma unroll
            for (int nt = 0; nt < 4; nt++) {
                int row = wm * 64 + mt * 16 + (lane >> 2);
                int col = wncol + nt * 8 + (lane & 3) * 2;
                *(float2*)&Cs[row * 132 + col] = make_float2(
                    (float)acc[mt][nt][0] * sav[mt][0] * sbv[nt][0],
                    (float)acc[mt][nt][1] * sav[mt][0] * sbv[nt][1]);
                *(float2*)&Cs[(row + 8) * 132 + col] = make_float2(
                    (float)acc[mt][nt][2] * sav[mt][1] * sbv[nt][0],
                    (float)acc[mt][nt][3] * sav[mt][1] * sbv[nt][1]);
            }
    }
    __syncthreads();

    const int r = tid >> 1, hf = tid & 1;
    float f[64];
    #pragma unroll
    for (int j = 0; j < 16; j++)
        *(float4*)&f[j * 4] = *(const float4*)&Cs[r * 132 + hf * 64 + j * 4];
    float mx = -CUDART_INF_F;
    #pragma unroll
    for (int j = 0; j < 64; j++) mx = fmaxf(mx, f[j]);
    float s = 0.f;
    #pragma unroll
    for (int j = 0; j < 64; j++) { f[j] = __expf(f[j] - mx); s += f[j]; }
    float inv = 1.f / s;
    #pragma unroll
    for (int j = 0; j < 64; j++) f[j] *= inv;
    __half* dst = attnOut + (size_t)(row0 + r) * DDIM + col0 + hf * 64;
    #pragma unroll
    for (int j = 0; j < 8; j++) {
        __half2 p0 = __floats2half2_rn(f[8*j+0], f[8*j+1]);
        __half2 p1 = __floats2half2_rn(f[8*j+2], f[8*j+3]);
        __half2 p2 = __floats2half2_rn(f[8*j+4], f[8*j+5]);
        __half2 p3 = __floats2half2_rn(f[8*j+6], f[8*j+7]);
        *(uint4*)(dst + 8*j) =
            make_uint4(*(uint32_t*)&p0, *(uint32_t*)&p1, *(uint32_t*)&p2, *(uint32_t*)&p3);
    }
    __syncthreads();
    float* red = (float*)sm;
    #pragma unroll
    for (int j = 0; j < 64; j++) red[(hf * 64 + j) * 129 + r] = f[j];
    __syncthreads();
    if (tid < 128) {
        float s2 = 0.f;
        #pragma unroll 8
        for (int rr = 0; rr < 128; rr++) s2 += red[tid * 129 + rr];
        atomicAdd(&redOut[batch * DDIM + col0 + tid], s2);
    }
}

// ---------------------------------------------------------------------------
// k_qx: per-row int8 quantization of x. One block per row (256 thr).
// ---------------------------------------------------------------------------
__global__ void __launch_bounds__(256)
k_qx(const float* __restrict__ x, int8_t* __restrict__ xq, float* __restrict__ sa) {
    __shared__ float wmax[8];
    __shared__ float bscale;
    const int n = blockIdx.x, tid = threadIdx.x;
    float4 v = ((const float4*)(x + (size_t)n * DDIM))[tid];
    float m = fmaxf(fmaxf(fabsf(v.x), fabsf(v.y)), fmaxf(fabsf(v.z), fabsf(v.w)));
    #pragma unroll
    for (int o = 16; o > 0; o >>= 1)
        m = fmaxf(m, __shfl_xor_sync(0xFFFFFFFFu, m, o));
    if ((tid & 31) == 0) wmax[tid >> 5] = m;
    __syncthreads();
    if (tid == 0) {
        float bm = wmax[0];
        #pragma unroll
        for (int i = 1; i < 8; i++) bm = fmaxf(bm, wmax[i]);
        bm = fmaxf(bm, 1e-30f);
        sa[n] = bm / 127.f;
        bscale = 127.f / bm;
    }
    __syncthreads();
    float qs = bscale;
    int i0 = __float2int_rn(v.x * qs), i1 = __float2int_rn(v.y * qs);
    int i2 = __float2int_rn(v.z * qs), i3 = __float2int_rn(v.w * qs);
    uint32_t p = ((uint32_t)i0 & 0xFF) | (((uint32_t)i1 & 0xFF) << 8) |
                 (((uint32_t)i2 & 0xFF) << 16) | (((uint32_t)i3) << 24);
    ((uint32_t*)xq)[(size_t)n * (DDIM/4) + tid] = p;
}

// ---------------------------------------------------------------------------
// k_q8: per-row int8 quantization of B1 (fp16 -> int8 + scale)
// ---------------------------------------------------------------------------
__global__ void __launch_bounds__(256)
k_q8(const __half* __restrict__ Bh, int8_t* __restrict__ Bq, float* __restrict__ sb) {
    __shared__ float wmax[8];
    __shared__ float bscale;
    const int n = blockIdx.x, tid = threadIdx.x;
    uint2 raw = ((const uint2*)(Bh + (size_t)n * DDIM))[tid];
    float2 f01 = __half22float2(*(__half2*)&raw.x);
    float2 f23 = __half22float2(*(__half2*)&raw.y);
    float m = fmaxf(fmaxf(fabsf(f01.x), fabsf(f01.y)), fmaxf(fabsf(f23.x), fabsf(f23.y)));
    #pragma unroll
    for (int o = 16; o > 0; o >>= 1)
        m = fmaxf(m, __shfl_xor_sync(0xFFFFFFFFu, m, o));
    if ((tid & 31) == 0) wmax[tid >> 5] = m;
    __syncthreads();
    if (tid == 0) {
        float bm = wmax[0];
        #pragma unroll
        for (int i = 1; i < 8; i++) bm = fmaxf(bm, wmax[i]);
        bm = fmaxf(bm, 1e-30f);
        sb[n] = bm / 127.f;
        bscale = 127.f / bm;
    }
    __syncthreads();
    float qs = bscale;
    int i0 = __float2int_rn(f01.x * qs), i1 = __float2int_rn(f01.y * qs);
    int i2 = __float2int_rn(f23.x * qs), i3 = __float2int_rn(f23.y * qs);
    uint32_t p = ((uint32_t)i0 & 0xFF) | (((uint32_t)i1 & 0xFF) << 8) |
                 (((uint32_t)i2 & 0xFF) << 16) | (((uint32_t)i3) << 24);
    ((uint32_t*)Bq)[(size_t)n * (DDIM/4) + tid] = p;
}

// ---------------------------------------------------------------------------
__global__ void k_zero(float* __restrict__ G, float* __restrict__ A) {
    int i = blockIdx.x * blockDim.x + threadIdx.x;
    if (i < BATCH*DDIM) { G[i] = 0.f; A[i] = 0.f; }
}

__global__ void __launch_bounds__(256)
k_wl(const float* __restrict__ wq, const float* __restrict__ kvl,
     __half* __restrict__ B1) {
    __shared__ float kvs[64][65];
    __shared__ float wseg[4][64];
    __shared__ __half wl[64][128];
    const int h = blockIdx.y, dbase = blockIdx.x * 128;
    const int tid = threadIdx.x;
    #pragma unroll
    for (int i = 0; i < 16; i++) {
        int idx = tid + i * 256;
        int r = idx >> 6, t = idx & 63;
        kvs[r][t] = kvl[(size_t)r * DDIM + h * HD + t];
    }
    __syncthreads();
    const int r = tid & 63, dsel = tid >> 6;
    for (int it = 0; it < 32; it++) {
        wseg[dsel][r] = wq[(size_t)(dbase + it * 4 + dsel) * DDIM + h * HD + r];
        __syncthreads();
        float s = 0.f;
        #pragma unroll
        for (int t = 0; t < 64; t++) s += wseg[dsel][t] * kvs[r][t];
        wl[r][it * 4 + dsel] = __float2half_rn(s * SCALE);
        __syncthreads();
    }
    #pragma unroll
    for (int i = 0; i < 16; i++) {
        int idx = tid + i * 256;
        int rr = idx >> 6, c2 = idx & 63;
        *(uint32_t*)&B1[(size_t)(h * HD + rr) * DDIM + dbase + c2 * 2] =
            *(uint32_t*)&wl[rr][c2 * 2];
    }
}

__global__ void __launch_bounds__(256)
k_p(const float* __restrict__ kvl, const float* __restrict__ wo,
    float* __restrict__ P) {
    __shared__ float kvs[64][65];
    __shared__ float woS[2][128];
    const int h = blockIdx.y, ebase = blockIdx.x * 128;
    const int tid = threadIdx.x;
    #pragma unroll
    for (int i = 0; i < 16; i++) {
        int idx = tid + i * 256;
        int r = idx >> 6, t = idx & 63;
        kvs[r][t] = kvl[(size_t)r * DDIM + h * HD + t];
    }
    __syncthreads();
    const int eloc = tid & 127, rbase = tid >> 7;
    float acc[32];
    #pragma unroll
    for (int i = 0; i < 32; i++) acc[i] = 0.f;
    for (int t2 = 0; t2 < 64; t2 += 2) {
        woS[rbase][eloc] = wo[(size_t)(h * HD + t2 + rbase) * DDIM + ebase + eloc];
        __syncthreads();
        #pragma unroll
        for (int tt = 0; tt < 2; tt++) {
            float w = woS[tt][eloc];
            #pragma unroll
            for (int i = 0; i < 32; i++)
                acc[i] += kvs[rbase + 2 * i][t2 + tt] * w;
        }
        __syncthreads();
    }
    #pragma unroll
    for (int i = 0; i < 32; i++)
        P[(size_t)(h * HD + rbase + 2 * i) * DDIM + ebase + eloc] = acc[i];
}

__global__ void k_tw1(const float* __restrict__ W, __half* __restrict__ WT) {
    __shared__ float t[32][33];
    int bx = blockIdx.x * 32, by = blockIdx.y * 32;
    int tx = threadIdx.x & 31, ty = threadIdx.x >> 5;
    #pragma unroll
    for (int i = 0; i < 4; i++)
        t[ty + 8*i][tx] = W[(size_t)(by + ty + 8*i)*DDIM + bx + tx];
    __syncthreads();
    #pragma unroll
    for (int i = 0; i < 4; i++)
        WT[(size_t)(bx + ty + 8*i)*DDIM + by + tx] = __float2half_rn(t[tx][ty + 8*i]);
}

__global__ void k_final(const float* __restrict__ w2, const float* __restrict__ b2,
                        const float* __restrict__ Gsum, const float* __restrict__ Asum,
                        const float* __restrict__ P, float* __restrict__ out) {
    int b = blockIdx.y;
    int e = blockIdx.x * 256 + threadIdx.x;
    __shared__ float gs[DDIM], as[DDIM];
    const float invS = 1.f / (float)SEQ;
    for (int i = threadIdx.x; i < DDIM; i += 256) {
        gs[i] = Gsum[b*DDIM + i] * invS;
        as[i] = Asum[b*DDIM + i] * invS;
    }
    __syncthreads();
    float a0 = 0.f, a1 = 0.f, a2 = 0.f, a3 = 0.f;
    for (int k = 0; k < DDIM; k += 4) {
        a0 = fmaf(gs[k  ], w2[(size_t)(k  )*DDIM + e], fmaf(as[k  ], P[(size_t)(k  )*DDIM + e], a0));
        a1 = fmaf(gs[k+1], w2[(size_t)(k+1)*DDIM + e], fmaf(as[k+1], P[(size_t)(k+1)*DDIM + e], a1));
        a2 = fmaf(gs[k+2], w2[(size_t)(k+2)*DDIM + e], fmaf(as[k+2], P[(size_t)(k+2)*DDIM + e], a2));
        a3 = fmaf(gs[k+3], w2[(size_t)(k+3)*DDIM + e], fmaf(as[k+3], P[(size_t)(k+3)*DDIM + e], a3));
    }
    out[b*DDIM + e] = b2[e] + ((a0 + a1) + (a2 + a3));
}

// ---------------------------------------------------------------------------
// Host launcher
// ---------------------------------------------------------------------------
extern "C" void kernel_launch(void* const* d_in, const int* in_sizes, int n_in,
                              void* d_out, int out_size) {
    const float* x   = (const float*)d_in[0];
    const float* wq  = (const float*)d_in[1];
    const float* kvl = (const float*)d_in[2];
    const float* wo  = (const float*)d_in[3];
    const float* w1  = (const float*)d_in[4];
    const float* b1  = (const float*)d_in[5];
    const float* w2  = (const float*)d_in[6];
    const float* b2  = (const float*)d_in[7];
    float* out = (float*)d_out;

    float *pP, *pG, *pA, *pSb, *pSa;
    __half *pW1T, *pB1, *pB2, *pAttnH;
    int8_t *pB1q, *pXq;
    cudaGetSymbolAddress((void**)&pP,     g_P);
    cudaGetSymbolAddress((void**)&pG,     g_Gsum);
    cudaGetSymbolAddress((void**)&pA,     g_Asum);
    cudaGetSymbolAddress((void**)&pW1T,   g_W1T);
    cudaGetSymbolAddress((void**)&pB1,    g_B1);
    cudaGetSymbolAddress((void**)&pB1q,   g_B1q);
    cudaGetSymbolAddress((void**)&pSb,    g_sbB);
    cudaGetSymbolAddress((void**)&pB2,    g_B2);
    cudaGetSymbolAddress((void**)&pXq,    g_xq);
    cudaGetSymbolAddress((void**)&pSa,    g_sa);
    cudaGetSymbolAddress((void**)&pAttnH, g_attnH);

    cudaFuncSetAttribute(wm_gemm<0,0>, cudaFuncAttributeMaxDynamicSharedMemorySize, SMEM_M1);
    cudaFuncSetAttribute(wm_gemm<2,1>, cudaFuncAttributeMaxDynamicSharedMemorySize, SMEM_M2);
    cudaFuncSetAttribute(wm_gemm_i8,   cudaFuncAttributeMaxDynamicSharedMemorySize, SMEM_M1);

    // 1. zero accumulators; quantize x (per-row int8)
    k_zero<<<(BATCH*DDIM + 255)/256, 256>>>(pG, pA);
    k_qx<<<NTOK, 256>>>(x, pXq, pSa);
    // 2. folded weights: B1 fp16 -> int8 + scales; P fp32
    k_wl<<<dim3(8, NHEAD), 256>>>(wq, kvl, pB1);
    k_q8<<<DDIM, 256>>>(pB1, pB1q, pSb);
    k_p <<<dim3(8, NHEAD), 256>>>(kvl, wo, pP);
    // 3. B2 = (P @ w1)^T fp16, on tensor cores
    k_tw1<<<dim3(32, 32), 256>>>(w1, pW1T);
    wm_gemm<0,0><<<dim3(8, 8), 256, SMEM_M1>>>(pP, nullptr, pW1T, nullptr, pB2, nullptr);
    // 4. attn = softmax(dequant(xq @ B1q)); Asum   [IMMA s8 k32 — rate probe]
    wm_gemm_i8<<<dim3(8, NTOK/128), 256, SMEM_M1>>>(pXq, pB1q, pSa, pSb, pAttnH, pA);
    // 5. Gsum += colsum(gelu(attn @ Q1 + b1))       [fp16 f32-accum, round-9]
    wm_gemm<2,1><<<dim3(8, NTOK/128), 256, SMEM_M2>>>(nullptr, pAttnH, pB2, b1, nullptr, pG);
    // 6. final tiny GEMMs + bias + residual mean
    k_final<<<dim3(4, BATCH), 256>>>(w2, b2, pG, pA, pP, out);
}

// round 16
// speedup vs baseline: 1.5150x; 1.5150x over previous
#include <cuda_runtime.h>
#include <cuda_fp16.h>
#include <cstdint>
#include <stdint.h>
#include <math.h>
#include <math_constants.h>

// Problem constants
#define BATCH  32
#define SEQ    4096
#define DDIM   1024
#define NTOK   (BATCH*SEQ)     // 131072
#define NHEAD  16
#define HD     64
#define RLAT   64
#define SCALE  0.125f          // R^-0.5

// ---------------------------------------------------------------------------
// Device scratch (static allocation; no cudaMalloc allowed)
// ---------------------------------------------------------------------------
__device__ float  g_P   [DDIM*DDIM];           // folded kv@wo (fp32, used by k_final)
__device__ __half g_W1T [DDIM*DDIM];           // w1^T fp16 (n-major, k contiguous)
__device__ __half g_B1  [DDIM*DDIM];           // Wl^T  fp16 (n-major, k contiguous)
__device__ __half g_B2  [DDIM*DDIM];           // Q1^T  fp16
__device__ __half g_attnH[(size_t)NTOK*DDIM];  // softmax(attn) fp16 (256 MB)
__device__ float  g_Gsum[BATCH*DDIM];
__device__ float  g_Asum[BATCH*DDIM];

// ---------------------------------------------------------------------------
// Portable PTX helpers (sm_80+ ISA — harness emits compute_103 PTX, so no
// tcgen05/TMA arch-specific instructions are available)
// ---------------------------------------------------------------------------
__device__ __forceinline__ uint32_t smem_u32(const void* p) {
    uint32_t a;
    asm("{ .reg .u64 t; cvta.to.shared.u64 t, %1; cvt.u32.u64 %0, t; }" : "=r"(a) : "l"(p));
    return a;
}
__device__ __forceinline__ void ldm_x4(uint32_t* r, uint32_t a) {
    asm volatile("ldmatrix.sync.aligned.m8n8.x4.shared.b16 {%0,%1,%2,%3}, [%4];"
        : "=r"(r[0]), "=r"(r[1]), "=r"(r[2]), "=r"(r[3]) : "r"(a));
}
__device__ __forceinline__ void mma16816(float* c, const uint32_t* a, const uint32_t* b) {
    asm volatile("mma.sync.aligned.m16n8k16.row.col.f32.f16.f16.f32 "
        "{%0,%1,%2,%3}, {%4,%5,%6,%7}, {%8,%9}, {%0,%1,%2,%3};"
        : "+f"(c[0]), "+f"(c[1]), "+f"(c[2]), "+f"(c[3])
        : "r"(a[0]), "r"(a[1]), "r"(a[2]), "r"(a[3]), "r"(b[0]), "r"(b[1]));
}
#define CP_ASYNC16(dst, src) \
    asm volatile("cp.async.cg.shared.global [%0], [%1], 16;" :: "r"(dst), "l"(src) : "memory")
#define CP_COMMIT() asm volatile("cp.async.commit_group;" ::: "memory")
#define CP_WAIT0()  asm volatile("cp.async.wait_group 0;" ::: "memory")

// 16B-unit XOR swizzle: row stride 64B (BK=32 fp16), unit u in 0..3
__device__ __forceinline__ int swz(int row, int u) {
    return row * 64 + ((u ^ ((row >> 1) & 3)) << 4);
}

// ---------------------------------------------------------------------------
// wm_gemm<MODE, AHALF>: C[128x128] = A @ B   [single-pass fp16 mma.sync]
//   A: fp32 (AHALF=0: LDG+convert+STS) or fp16 (AHALF=1: pure cp.async)
//   MODE 0: store C^T as fp16 to outH  (used for B2 = Q1^T = (P@w1)^T)
//   MODE 1: per-head softmax, store attn fp16, colsum -> redOut (Asum)
//   MODE 2: +bias, exact gelu, colsum -> redOut (Gsum); nothing stored
// 256 threads = 8 warps (2 M-halves x 4 N-quarters), warp tile 64x32, BK=32.
// Stage: A 8KB + B 8KB = 16KB, double buffered. 2 CTAs/SM.
// ---------------------------------------------------------------------------
#define NKC      32            // K chunks of 32
#define STG      16384         // bytes per stage
#define OFF_B    8192
#define SMEM_M1  67584         // epilogue Cs 128*132*4 (>= 2*STG)
#define SMEM_M2  32768         // 2*STG (red fits inside)

template<int MODE, int AHALF>
__global__ void __launch_bounds__(256, 2)
wm_gemm(const float* __restrict__ Af, const __half* __restrict__ Ah16,
        const __half* __restrict__ B,
        const float* __restrict__ bias,
        __half* __restrict__ outH, float* __restrict__ redOut)
{
    extern __shared__ char sm[];
    const uint32_t smb = smem_u32(sm);
    const int tid = threadIdx.x;
    const int lane = tid & 31, wid = tid >> 5;
    const int wm = wid & 1;                    // warp M half (0/1)
    const int wncol = (wid >> 1) * 32;         // warp N base col
    const int row0 = blockIdx.y * 128, col0 = blockIdx.x * 128;

    float acc[4][4][4];
    #pragma unroll
    for (int i = 0; i < 4; i++)
        #pragma unroll
        for (int j = 0; j < 4; j++)
            #pragma unroll
            for (int r = 0; r < 4; r++) acc[i][j][r] = 0.f;

    // per-thread staging unit coords (2 x 16B units per region)
    const int u0r = (tid + 0)   >> 2, u0u = (tid + 0)   & 3;
    const int u1r = (tid + 256) >> 2, u1u = (tid + 256) & 3;

    auto loadB = [&](int kc, int s) {
        uint32_t base = smb + s * STG;
        CP_ASYNC16(base + OFF_B + swz(u0r, u0u), B + (size_t)(col0 + u0r) * DDIM + kc * 32 + u0u * 8);
        CP_ASYNC16(base + OFF_B + swz(u1r, u1u), B + (size_t)(col0 + u1r) * DDIM + kc * 32 + u1u * 8);
    };
    auto loadA_async = [&](int kc, int s) {
        uint32_t base = smb + s * STG;
        CP_ASYNC16(base + swz(u0r, u0u), Ah16 + (size_t)(row0 + u0r) * DDIM + kc * 32 + u0u * 8);
        CP_ASYNC16(base + swz(u1r, u1u), Ah16 + (size_t)(row0 + u1r) * DDIM + kc * 32 + u1u * 8);
    };
    auto loadA_f32 = [&](int kc, float4* av) {
        const float* a0 = Af + (size_t)(row0 + u0r) * DDIM + kc * 32 + u0u * 8;
        const float* a1 = Af + (size_t)(row0 + u1r) * DDIM + kc * 32 + u1u * 8;
        av[0] = *(const float4*)(a0);
        av[1] = *(const float4*)(a0 + 4);
        av[2] = *(const float4*)(a1);
        av[3] = *(const float4*)(a1 + 4);
    };
    auto stsA = [&](const float4* av, int s) {
        char* base = sm + (size_t)s * STG;
        #pragma unroll
        for (int i = 0; i < 2; i++) {
            float4 v0 = av[2*i], v1 = av[2*i+1];
            __half2 h0 = __floats2half2_rn(v0.x, v0.y);
            __half2 h1 = __floats2half2_rn(v0.z, v0.w);
            __half2 h2 = __floats2half2_rn(v1.x, v1.y);
            __half2 h3 = __floats2half2_rn(v1.z, v1.w);
            int r = i ? u1r : u0r, u = i ? u1u : u0u;
            *(uint4*)(base + swz(r, u)) =
                make_uint4(*(uint32_t*)&h0, *(uint32_t*)&h1, *(uint32_t*)&h2, *(uint32_t*)&h3);
        }
    };

    // ---- prologue: chunk 0
    loadB(0, 0);
    if (AHALF) loadA_async(0, 0);
    CP_COMMIT();
    if (!AHALF) { float4 av[4]; loadA_f32(0, av); stsA(av, 0); }
    CP_WAIT0(); __syncthreads();

    // ---- main loop
    for (int kc = 0; kc < NKC; kc++) {
        const int cur = kc & 1;
        float4 av[4];
        if (kc < NKC - 1) {
            loadB(kc + 1, cur ^ 1);
            if (AHALF) loadA_async(kc + 1, cur ^ 1);
            CP_COMMIT();
            if (!AHALF) loadA_f32(kc + 1, av);
        }

        const uint32_t sA = smb + cur * STG;
        #pragma unroll
        for (int kk = 0; kk < 2; kk++) {
            uint32_t ah[4][4], bh[4][2];
            #pragma unroll
            for (int mt = 0; mt < 4; mt++) {
                int arow = wm * 64 + mt * 16 + (lane & 7) + ((lane >> 3) & 1) * 8;
                int au   = kk * 2 + (lane >> 4);
                ldm_x4(ah[mt], sA + swz(arow, au));
            }
            #pragma unroll
            for (int nt2 = 0; nt2 < 2; nt2++) {
                int brow = wncol + nt2 * 16 + ((lane >> 4) << 3) + (lane & 7);
                int bu   = kk * 2 + ((lane >> 3) & 1);
                uint32_t r4[4];
                ldm_x4(r4, sA + OFF_B + swz(brow, bu));
                bh[2*nt2][0] = r4[0]; bh[2*nt2][1] = r4[1];
                bh[2*nt2+1][0] = r4[2]; bh[2*nt2+1][1] = r4[3];
            }
            #pragma unroll
            for (int mt = 0; mt < 4; mt++)
                #pragma unroll
                for (int nt = 0; nt < 4; nt++)
                    mma16816(acc[mt][nt], ah[mt], bh[nt]);
        }
        if (!AHALF && kc < NKC - 1) stsA(av, cur ^ 1);
        CP_WAIT0(); __syncthreads();
    }

    const int batch = row0 >> 12;   // SEQ = 4096

    if (MODE == 0 || MODE == 1) {
        // stage C tile to smem (stride 132 floats: float4-aligned rows)
        float* Cs = (float*)sm;
        #pragma unroll
        for (int mt = 0; mt < 4; mt++)
            #pragma unroll
            for (int nt = 0; nt < 4; nt++) {
                int row = wm * 64 + mt * 16 + (lane >> 2);
                int col = wncol + nt * 8 + (lane & 3) * 2;
                *(float2*)&Cs[row * 132 + col]       = make_float2(acc[mt][nt][0], acc[mt][nt][1]);
                *(float2*)&Cs[(row + 8) * 132 + col] = make_float2(acc[mt][nt][2], acc[mt][nt][3]);
            }
        __syncthreads();

        if (MODE == 0) {
            // transposed fp16 store: outH[(col0+n)*DDIM + row0+m]
            const int n = tid >> 1, half = tid & 1;
            __half* dst = outH + (size_t)(col0 + n) * DDIM + row0 + half * 64;
            #pragma unroll
            for (int j = 0; j < 32; j++) {
                __half2 p = __floats2half2_rn(Cs[(half*64 + 2*j    ) * 132 + n],
                                              Cs[(half*64 + 2*j + 1) * 132 + n]);
                ((uint32_t*)dst)[j] = *(uint32_t*)&p;
            }
        }

        if (MODE == 1) {
            // per-thread softmax over one 64-latent head segment
            const int r = tid >> 1, hf = tid & 1;
            float f[64];
            #pragma unroll
            for (int j = 0; j < 16; j++)
                *(float4*)&f[j * 4] = *(const float4*)&Cs[r * 132 + hf * 64 + j * 4];
            float mx = -CUDART_INF_F;
            #pragma unroll
            for (int j = 0; j < 64; j++) mx = fmaxf(mx, f[j]);
            float s = 0.f;
            #pragma unroll
            for (int j = 0; j < 64; j++) { f[j] = __expf(f[j] - mx); s += f[j]; }
            float inv = 1.f / s;
            #pragma unroll
            for (int j = 0; j < 64; j++) f[j] *= inv;
            // store attn as fp16 (GEMM2 consumes directly via cp.async)
            __half* dst = outH + (size_t)(row0 + r) * DDIM + col0 + hf * 64;
            #pragma unroll
            for (int j = 0; j < 8; j++) {
                __half2 p0 = __floats2half2_rn(f[8*j+0], f[8*j+1]);
                __half2 p1 = __floats2half2_rn(f[8*j+2], f[8*j+3]);
                __half2 p2 = __floats2half2_rn(f[8*j+4], f[8*j+5]);
                __half2 p3 = __floats2half2_rn(f[8*j+6], f[8*j+7]);
                *(uint4*)(dst + 8*j) =
                    make_uint4(*(uint32_t*)&p0, *(uint32_t*)&p1, *(uint32_t*)&p2, *(uint32_t*)&p3);
            }
            __syncthreads();           // all Cs reads done; reuse as red[col][row]
            float* red = (float*)sm;
            #pragma unroll
            for (int j = 0; j < 64; j++) red[(hf * 64 + j) * 129 + r] = f[j];
            __syncthreads();
            if (tid < 128) {
                float s2 = 0.f;
                #pragma unroll 8
                for (int rr = 0; rr < 128; rr++) s2 += red[tid * 129 + rr];
                atomicAdd(&redOut[batch * DDIM + col0 + tid], s2);
            }
        }
    }

    if (MODE == 2) {
        float bv[4][2];
        #pragma unroll
        for (int nt = 0; nt < 4; nt++)
            #pragma unroll
            for (int p = 0; p < 2; p++)
                bv[nt][p] = __ldg(&bias[col0 + wncol + nt * 8 + (lane & 3) * 2 + p]);
        float cs[4][2];
        #pragma unroll
        for (int nt = 0; nt < 4; nt++) { cs[nt][0] = 0.f; cs[nt][1] = 0.f; }
        #pragma unroll
        for (int mt = 0; mt < 4; mt++)
            #pragma unroll
            for (int nt = 0; nt < 4; nt++)
                #pragma unroll
                for (int rg = 0; rg < 4; rg++) {
                    float z = acc[mt][nt][rg] + bv[nt][rg & 1];
                    float g = 0.5f * z * (1.f + erff(z * 0.70710678118654752f));
                    cs[nt][rg & 1] += g;
                }
        float* red = (float*)sm;   // [128 cols][17 slots]
        const int slot = wm * 8 + (lane >> 2);
        __syncthreads();
        #pragma unroll
        for (int nt = 0; nt < 4; nt++)
            #pragma unroll
            for (int p = 0; p < 2; p++)
                red[(wncol + nt * 8 + (lane & 3) * 2 + p) * 17 + slot] = cs[nt][p];
        __syncthreads();
        if (tid < 128) {
            float s2 = 0.f;
            #pragma unroll
            for (int t = 0; t < 16; t++) s2 += red[tid * 17 + t];
            atomicAdd(&redOut[batch * DDIM + col0 + tid], s2);
        }
    }
}

// ---------------------------------------------------------------------------
// k_zero
// ---------------------------------------------------------------------------
__global__ void k_zero(float* __restrict__ G, float* __restrict__ A) {
    int i = blockIdx.x * blockDim.x + threadIdx.x;
    if (i < BATCH*DDIM) { G[i] = 0.f; A[i] = 0.f; }
}

// ---------------------------------------------------------------------------
// k_wl: B1[(h*64+r)][d] = fp16(SCALE * wq[d,h*64+:]·kvl[r,h*64+:])
// grid (8 d-chunks, 16 h), 256 threads. kv segment loaded once per block.
// ---------------------------------------------------------------------------
__global__ void __launch_bounds__(256)
k_wl(const float* __restrict__ wq, const float* __restrict__ kvl,
     __half* __restrict__ B1) {
    __shared__ float kvs[64][65];
    __shared__ float wseg[4][64];
    __shared__ __half wl[64][128];
    const int h = blockIdx.y, dbase = blockIdx.x * 128;
    const int tid = threadIdx.x;
    #pragma unroll
    for (int i = 0; i < 16; i++) {
        int idx = tid + i * 256;
        int r = idx >> 6, t = idx & 63;
        kvs[r][t] = kvl[(size_t)r * DDIM + h * HD + t];
    }
    __syncthreads();
    const int r = tid & 63, dsel = tid >> 6;
    for (int it = 0; it < 32; it++) {
        wseg[dsel][r] = wq[(size_t)(dbase + it * 4 + dsel) * DDIM + h * HD + r];
        __syncthreads();
        float s = 0.f;
        #pragma unroll
        for (int t = 0; t < 64; t++) s += wseg[dsel][t] * kvs[r][t];
        wl[r][it * 4 + dsel] = __float2half_rn(s * SCALE);
        __syncthreads();
    }
    // coalesced write: B1 rows (h*64+r), cols dbase..dbase+128
    #pragma unroll
    for (int i = 0; i < 16; i++) {
        int idx = tid + i * 256;       // 4096 uint32 = 8192 halves
        int rr = idx >> 6, c2 = idx & 63;
        *(uint32_t*)&B1[(size_t)(h * HD + rr) * DDIM + dbase + c2 * 2] =
            *(uint32_t*)&wl[rr][c2 * 2];
    }
}

// ---------------------------------------------------------------------------
// k_p: P[(h*64+r)][e] = sum_t kvl[r, h*64+t] * wo[h*64+t, e]   (fp32)
// grid (8 e-chunks, 16 h), 256 threads. wo streamed once total (4MB).
// ---------------------------------------------------------------------------
__global__ void __launch_bounds__(256)
k_p(const float* __restrict__ kvl, const float* __restrict__ wo,
    float* __restrict__ P) {
    __shared__ float kvs[64][65];
    __shared__ float woS[2][128];
    const int h = blockIdx.y, ebase = blockIdx.x * 128;
    const int tid = threadIdx.x;
    #pragma unroll
    for (int i = 0; i < 16; i++) {
        int idx = tid + i * 256;
        int r = idx >> 6, t = idx & 63;
        kvs[r][t] = kvl[(size_t)r * DDIM + h * HD + t];
    }
    __syncthreads();
    const int eloc = tid & 127, rbase = tid >> 7;   // rbase 0/1
    float acc[32];
    #pragma unroll
    for (int i = 0; i < 32; i++) acc[i] = 0.f;
    for (int t2 = 0; t2 < 64; t2 += 2) {
        woS[rbase][eloc] = wo[(size_t)(h * HD + t2 + rbase) * DDIM + ebase + eloc];
        __syncthreads();
        #pragma unroll
        for (int tt = 0; tt < 2; tt++) {
            float w = woS[tt][eloc];
            #pragma unroll
            for (int i = 0; i < 32; i++)
                acc[i] += kvs[rbase + 2 * i][t2 + tt] * w;
        }
        __syncthreads();
    }
    #pragma unroll
    for (int i = 0; i < 32; i++)
        P[(size_t)(h * HD + rbase + 2 * i) * DDIM + ebase + eloc] = acc[i];
}

// ---------------------------------------------------------------------------
// k_tw1: W1T[n][k] = fp16(w1[k][n])   (transpose, fp32 -> fp16)
// ---------------------------------------------------------------------------
__global__ void k_tw1(const float* __restrict__ W, __half* __restrict__ WT) {
    __shared__ float t[32][33];
    int bx = blockIdx.x * 32, by = blockIdx.y * 32;
    int tx = threadIdx.x & 31, ty = threadIdx.x >> 5;  // 8 rows
    #pragma unroll
    for (int i = 0; i < 4; i++)
        t[ty + 8*i][tx] = W[(size_t)(by + ty + 8*i)*DDIM + bx + tx];
    __syncthreads();
    #pragma unroll
    for (int i = 0; i < 4; i++)
        WT[(size_t)(bx + ty + 8*i)*DDIM + by + tx] = __float2half_rn(t[tx][ty + 8*i]);
}

// ---------------------------------------------------------------------------
// k_final: out[b,e] = b2[e] + (Gsum[b]/S) @ w2[:,e] + (Asum[b]/S) @ P[:,e]
// ---------------------------------------------------------------------------
__global__ void k_final(const float* __restrict__ w2, const float* __restrict__ b2,
                        const float* __restrict__ Gsum, const float* __restrict__ Asum,
                        const float* __restrict__ P, float* __restrict__ out) {
    int b = blockIdx.y;
    int e = blockIdx.x * 256 + threadIdx.x;
    __shared__ float gs[DDIM], as[DDIM];
    const float invS = 1.f / (float)SEQ;
    for (int i = threadIdx.x; i < DDIM; i += 256) {
        gs[i] = Gsum[b*DDIM + i] * invS;
        as[i] = Asum[b*DDIM + i] * invS;
    }
    __syncthreads();
    float a0 = 0.f, a1 = 0.f, a2 = 0.f, a3 = 0.f;
    for (int k = 0; k < DDIM; k += 4) {
        a0 = fmaf(gs[k  ], w2[(size_t)(k  )*DDIM + e], fmaf(as[k  ], P[(size_t)(k  )*DDIM + e], a0));
        a1 = fmaf(gs[k+1], w2[(size_t)(k+1)*DDIM + e], fmaf(as[k+1], P[(size_t)(k+1)*DDIM + e], a1));
        a2 = fmaf(gs[k+2], w2[(size_t)(k+2)*DDIM + e], fmaf(as[k+2], P[(size_t)(k+2)*DDIM + e], a2));
        a3 = fmaf(gs[k+3], w2[(size_t)(k+3)*DDIM + e], fmaf(as[k+3], P[(size_t)(k+3)*DDIM + e], a3));
    }
    out[b*DDIM + e] = b2[e] + ((a0 + a1) + (a2 + a3));
}

// ---------------------------------------------------------------------------
// Host launcher
// ---------------------------------------------------------------------------
extern "C" void kernel_launch(void* const* d_in, const int* in_sizes, int n_in,
                              void* d_out, int out_size) {
    const float* x   = (const float*)d_in[0];
    const float* wq  = (const float*)d_in[1];
    const float* kvl = (const float*)d_in[2];
    const float* wo  = (const float*)d_in[3];
    const float* w1  = (const float*)d_in[4];
    const float* b1  = (const float*)d_in[5];
    const float* w2  = (const float*)d_in[6];
    const float* b2  = (const float*)d_in[7];
    float* out = (float*)d_out;

    float *pP, *pG, *pA;
    __half *pW1T, *pB1, *pB2, *pAttnH;
    cudaGetSymbolAddress((void**)&pP,     g_P);
    cudaGetSymbolAddress((void**)&pG,     g_Gsum);
    cudaGetSymbolAddress((void**)&pA,     g_Asum);
    cudaGetSymbolAddress((void**)&pW1T,   g_W1T);
    cudaGetSymbolAddress((void**)&pB1,    g_B1);
    cudaGetSymbolAddress((void**)&pB2,    g_B2);
    cudaGetSymbolAddress((void**)&pAttnH, g_attnH);

    cudaFuncSetAttribute(wm_gemm<0,0>, cudaFuncAttributeMaxDynamicSharedMemorySize, SMEM_M1);
    cudaFuncSetAttribute(wm_gemm<1,0>, cudaFuncAttributeMaxDynamicSharedMemorySize, SMEM_M1);
    cudaFuncSetAttribute(wm_gemm<2,1>, cudaFuncAttributeMaxDynamicSharedMemorySize, SMEM_M2);

    // 1. zero accumulators
    k_zero<<<(BATCH*DDIM + 255)/256, 256>>>(pG, pA);
    // 2. folded weights: B1 (fp16 transposed) and P (fp32)
    k_wl<<<dim3(8, NHEAD), 256>>>(wq, kvl, pB1);
    k_p <<<dim3(8, NHEAD), 256>>>(kvl, wo, pP);
    // 3. B2 = (P @ w1)^T fp16, on tensor cores
    k_tw1<<<dim3(32, 32), 256>>>(w1, pW1T);
    wm_gemm<0,0><<<dim3(8, 8), 256, SMEM_M1>>>(pP, nullptr, pW1T, nullptr, pB2, nullptr);
    // 4. attn = softmax(x @ Wl); Asum accumulated  [mma.sync fp16 x1]
    wm_gemm<1,0><<<dim3(8, NTOK/128), 256, SMEM_M1>>>(x, nullptr, pB1, nullptr, pAttnH, pA);
    // 5. Gsum += colsum(gelu(attn @ Q1 + b1))       [mma.sync fp16 x1, A=fp16]
    wm_gemm<2,1><<<dim3(8, NTOK/128), 256, SMEM_M2>>>(nullptr, pAttnH, pB2, b1, nullptr, pG);
    // 6. final tiny GEMMs + bias + residual mean
    k_final<<<dim3(4, BATCH), 256>>>(w2, b2, pG, pA, pP, out);
}